// round 15
// baseline (speedup 1.0000x reference)
#include <cuda_runtime.h>
#include <cuda_pipeline.h>
#include <math.h>

#define Bq   8
#define Hq   8
#define Lq   2048
#define Dq   64
#define Uq   40
#define BH   64
#define CTXN (BH*Uq*Dq)
#define NCH  4

// scratch (no allocations allowed)
__device__ float g_M[BH*Lq];
__device__ int   g_top[BH*Uq];
__device__ float g_part[NCH*CTXN];

// ---------------------------------------------------------------------------
// Kernel 1: M[bh,l] = max_s(q·k[idx]) - sum_s(q·k[idx]) / L
// Same inner loop as R8; block = 1024 threads = 32 l's of ONE bh so the
// block's 1280 gathered rows (of 2048) overlap ~26% -> L1 capture.
// ---------------------------------------------------------------------------
__global__ __launch_bounds__(1024) void k_M(const float* __restrict__ q,
                                            const float* __restrict__ kk,
                                            const int* __restrict__ idx) {
    int gw   = (blockIdx.x * blockDim.x + threadIdx.x) >> 5;   // bh*Lq + l
    int lane = threadIdx.x & 31;
    int g = lane >> 3;          // sample slot 0..3
    int e = lane & 7;           // 32B chunk 0..7
    int bh = gw >> 11;
    int l  = gw & (Lq - 1);

    const float*  kbase = kk + (size_t)bh*Lq*Dq;
    const float4* qrow  = (const float4*)(q + ((size_t)bh*Lq + l)*Dq);

    const float4 q0 = __ldg(qrow + 2*e);
    const float4 q1 = __ldg(qrow + 2*e + 1);

    const int* irow = idx + l*Uq;
    float mx = -INFINITY, sm = 0.f;

    #pragma unroll
    for (int i = 0; i < Uq/4; ++i) {
        int j = __ldg(irow + 4*i + g);
        const float4* kr = (const float4*)(kbase + (size_t)j*Dq);
        float4 a = __ldg(kr + 2*e);
        float4 b = __ldg(kr + 2*e + 1);
        float p = q0.x*a.x;
        p = fmaf(q0.y, a.y, p); p = fmaf(q0.z, a.z, p); p = fmaf(q0.w, a.w, p);
        p = fmaf(q1.x, b.x, p); p = fmaf(q1.y, b.y, p);
        p = fmaf(q1.z, b.z, p); p = fmaf(q1.w, b.w, p);
        p += __shfl_xor_sync(0xffffffffu, p, 4);
        p += __shfl_xor_sync(0xffffffffu, p, 2);
        p += __shfl_xor_sync(0xffffffffu, p, 1);
        mx = fmaxf(mx, p); sm += p;
    }
    mx = fmaxf(mx, __shfl_xor_sync(0xffffffffu, mx, 8));
    sm += __shfl_xor_sync(0xffffffffu, sm, 8);
    mx = fmaxf(mx, __shfl_xor_sync(0xffffffffu, mx, 16));
    sm += __shfl_xor_sync(0xffffffffu, sm, 16);

    if (lane == 0) g_M[gw] = mx - sm * (1.0f / (float)Lq);
}

// ---------------------------------------------------------------------------
// Kernel 2: top-40 per (bh), per-warp top-40 + 8-way merge (R10 proven)
// ---------------------------------------------------------------------------
__global__ __launch_bounds__(256) void k_topk() {
    __shared__ float cand_v[8][Uq];
    __shared__ int   cand_i[8][Uq];
    int bh = blockIdx.x, t = threadIdx.x;
    int w = t >> 5, lane = t & 31;
    const unsigned full = 0xffffffffu;

    float vals[8]; int idxs[8];
    #pragma unroll
    for (int ii = 0; ii < 8; ++ii) {
        int i = w*256 + ii*32 + lane;
        vals[ii] = g_M[bh*Lq + i];
        idxs[ii] = i;
    }

    for (int r = 0; r < Uq; ++r) {
        float bv = vals[0]; int bi = idxs[0]; int bs = 0;
        #pragma unroll
        for (int ii = 1; ii < 8; ++ii) {
            if (vals[ii] > bv || (vals[ii] == bv && idxs[ii] < bi)) {
                bv = vals[ii]; bi = idxs[ii]; bs = ii;
            }
        }
        float wv = bv; int wi = bi;
        #pragma unroll
        for (int o = 16; o > 0; o >>= 1) {
            float xv = __shfl_xor_sync(full, wv, o);
            int   xi = __shfl_xor_sync(full, wi, o);
            if (xv > wv || (xv == wv && xi < wi)) { wv = xv; wi = xi; }
        }
        if (wi == bi) vals[bs] = -INFINITY;
        if (lane == 0) { cand_v[w][r] = wv; cand_i[w][r] = wi; }
    }
    __syncthreads();

    if (w == 0 && lane < 8) {
        int head = 0;
        float hv = cand_v[lane][0];
        int   hi = cand_i[lane][0];
        for (int r = 0; r < Uq; ++r) {
            float bv = hv; int bi = hi; int bl = lane;
            #pragma unroll
            for (int o = 4; o > 0; o >>= 1) {
                float xv = __shfl_xor_sync(0xffu, bv, o);
                int   xi = __shfl_xor_sync(0xffu, bi, o);
                int   xl = __shfl_xor_sync(0xffu, bl, o);
                if (xv > bv || (xv == bv && xi < bi)) { bv = xv; bi = xi; bl = xl; }
            }
            if (lane == 0) g_top[bh*Uq + r] = bi;
            if (lane == bl) {
                head++;
                hv = (head < Uq) ? cand_v[lane][head] : -INFINITY;
                hi = (head < Uq) ? cand_i[lane][head] : 0x7fffffff;
            }
        }
    }
}

// ---------------------------------------------------------------------------
// Kernel 3: scores, 5x4 register-tiled @ 256 threads (R6/R12 proven)
// ---------------------------------------------------------------------------
__global__ __launch_bounds__(256) void k_scores(const float* __restrict__ q,
                                                const float* __restrict__ kk,
                                                float* __restrict__ attn) {
    __shared__ float qs[Uq][68];
    __shared__ float ks[128][68];
    int bh = blockIdx.y, tile = blockIdx.x, t = threadIdx.x;
    int w = t >> 5, lane = t & 31;

    const float* qb = q  + (size_t)bh*Lq*Dq;
    const float* kb = kk + ((size_t)bh*Lq + tile*128)*Dq;

    for (int i = t; i < Uq*16; i += 256) {
        int r = i >> 4, c4 = i & 15;
        float4 val = *(const float4*)(qb + (size_t)g_top[bh*Uq + r]*Dq + c4*4);
        *(float4*)&qs[r][c4*4] = val;
    }
    for (int i = t; i < 128*16; i += 256) {
        int l = i >> 4, c4 = i & 15;
        *(float4*)&ks[l][c4*4] = ((const float4*)(kb + (size_t)l*Dq))[c4];
    }
    __syncthreads();

    float acc[5][4] = {};
    #pragma unroll 4
    for (int c = 0; c < 64; c += 4) {
        float4 kr[4];
        #pragma unroll
        for (int j = 0; j < 4; ++j) kr[j] = *(const float4*)&ks[lane + 32*j][c];
        #pragma unroll
        for (int ji = 0; ji < 5; ++ji) {
            float4 qr = *(const float4*)&qs[5*w + ji][c];
            #pragma unroll
            for (int jl = 0; jl < 4; ++jl) {
                acc[ji][jl] = fmaf(qr.x, kr[jl].x, acc[ji][jl]);
                acc[ji][jl] = fmaf(qr.y, kr[jl].y, acc[ji][jl]);
                acc[ji][jl] = fmaf(qr.z, kr[jl].z, acc[ji][jl]);
                acc[ji][jl] = fmaf(qr.w, kr[jl].w, acc[ji][jl]);
            }
        }
    }
    #pragma unroll
    for (int ji = 0; ji < 5; ++ji) {
        int i = 5*w + ji;
        #pragma unroll
        for (int jl = 0; jl < 4; ++jl)
            attn[((size_t)bh*Uq + i)*Lq + tile*128 + lane + 32*jl] = acc[ji][jl] * 0.125f;
    }
}

// ---------------------------------------------------------------------------
// Kernel 4: row softmax, shfl reductions (R8/R12 proven)
// ---------------------------------------------------------------------------
__global__ __launch_bounds__(256) void k_softmax(float* __restrict__ attn) {
    __shared__ float wred[8];
    int row = blockIdx.x, t = threadIdx.x;
    int w = t >> 5, lane = t & 31;
    float* a = attn + (size_t)row * Lq;

    float4 v0 = ((float4*)a)[t];
    float4 v1 = ((float4*)a)[t + 256];

    float mx = fmaxf(fmaxf(fmaxf(v0.x, v0.y), fmaxf(v0.z, v0.w)),
                     fmaxf(fmaxf(v1.x, v1.y), fmaxf(v1.z, v1.w)));
    #pragma unroll
    for (int o = 16; o > 0; o >>= 1) mx = fmaxf(mx, __shfl_xor_sync(0xffffffffu, mx, o));
    if (lane == 0) wred[w] = mx;
    __syncthreads();
    mx = wred[0];
    #pragma unroll
    for (int j = 1; j < 8; ++j) mx = fmaxf(mx, wred[j]);
    __syncthreads();

    v0.x = expf(v0.x - mx); v0.y = expf(v0.y - mx);
    v0.z = expf(v0.z - mx); v0.w = expf(v0.w - mx);
    v1.x = expf(v1.x - mx); v1.y = expf(v1.y - mx);
    v1.z = expf(v1.z - mx); v1.w = expf(v1.w - mx);

    float s = v0.x + v0.y + v0.z + v0.w + v1.x + v1.y + v1.z + v1.w;
    #pragma unroll
    for (int o = 16; o > 0; o >>= 1) s += __shfl_xor_sync(0xffffffffu, s, o);
    if (lane == 0) wred[w] = s;
    __syncthreads();
    s = wred[0];
    #pragma unroll
    for (int j = 1; j < 8; ++j) s += wred[j];
    float inv = 1.0f / s;

    v0.x *= inv; v0.y *= inv; v0.z *= inv; v0.w *= inv;
    v1.x *= inv; v1.y *= inv; v1.z *= inv; v1.w *= inv;
    ((float4*)a)[t]       = v0;
    ((float4*)a)[t + 256] = v1;
}

// ---------------------------------------------------------------------------
// k_ctx tile fill via cp.async (R8 proven)
// ---------------------------------------------------------------------------
__device__ __forceinline__ void ctx_fill(float* vdst, float* adst,
                                         const float* __restrict__ vb,
                                         const float* __restrict__ ab,
                                         int l0, int t) {
    for (int i = t; i < 1024; i += 320) {
        int k = i >> 4, c4 = i & 15;
        __pipeline_memcpy_async(vdst + (size_t)k*64 + c4*4,
                                vb + (size_t)(l0 + k)*Dq + c4*4, 16);
    }
    for (int i = t; i < 640; i += 320) {
        int r = i >> 4, c4 = i & 15;
        __pipeline_memcpy_async(adst + (size_t)r*64 + c4*4,
                                ab + (size_t)r*Lq + l0 + c4*4, 16);
    }
    __pipeline_commit();
}

// ---------------------------------------------------------------------------
// Kernel 5: context partials, cp.async double-buffered; NCH=4 (R14 proven)
// ---------------------------------------------------------------------------
__global__ __launch_bounds__(320) void k_ctx(const float* __restrict__ v,
                                             const float* __restrict__ attn) {
    extern __shared__ float smc[];
    float* vsm0 = smc;
    float* vsm1 = smc + 4096;
    float* a_sm0 = smc + 8192;
    float* a_sm1 = smc + 8192 + 2560;
    int bh = blockIdx.y, ch = blockIdx.x, t = threadIdx.x;
    int w = t >> 5, lane = t & 31;

    const float* vb = v    + (size_t)bh*Lq*Dq;
    const float* ab = attn + (size_t)bh*Uq*Lq;

    float2 c0 = {0.f,0.f}, c1 = {0.f,0.f}, c2 = {0.f,0.f}, c3 = {0.f,0.f};

    ctx_fill(vsm0, a_sm0, vb, ab, ch*512, t);

    #pragma unroll
    for (int tl = 0; tl < 8; ++tl) {
        if (tl < 7) {
            ctx_fill((tl & 1) ? vsm0 : vsm1, (tl & 1) ? a_sm0 : a_sm1,
                     vb, ab, ch*512 + (tl+1)*64, t);
            __pipeline_wait_prior(1);
        } else {
            __pipeline_wait_prior(0);
        }
        __syncthreads();
        const float* vs = (tl & 1) ? vsm1 : vsm0;
        const float* as = (tl & 1) ? a_sm1 : a_sm0;
        #pragma unroll 4
        for (int k4 = 0; k4 < 16; ++k4) {
            float4 a0 = *(const float4*)&as[(4*w+0)*64 + 4*k4];
            float4 a1 = *(const float4*)&as[(4*w+1)*64 + 4*k4];
            float4 a2 = *(const float4*)&as[(4*w+2)*64 + 4*k4];
            float4 a3 = *(const float4*)&as[(4*w+3)*64 + 4*k4];
            #pragma unroll
            for (int j = 0; j < 4; ++j) {
                int k = 4*k4 + j;
                float2 vv = *(const float2*)&vs[(size_t)k*64 + 2*lane];
                float w0 = (j==0)?a0.x:(j==1)?a0.y:(j==2)?a0.z:a0.w;
                float w1 = (j==0)?a1.x:(j==1)?a1.y:(j==2)?a1.z:a1.w;
                float w2 = (j==0)?a2.x:(j==1)?a2.y:(j==2)?a2.z:a2.w;
                float w3 = (j==0)?a3.x:(j==1)?a3.y:(j==2)?a3.z:a3.w;
                c0.x = fmaf(w0, vv.x, c0.x); c0.y = fmaf(w0, vv.y, c0.y);
                c1.x = fmaf(w1, vv.x, c1.x); c1.y = fmaf(w1, vv.y, c1.y);
                c2.x = fmaf(w2, vv.x, c2.x); c2.y = fmaf(w2, vv.y, c2.y);
                c3.x = fmaf(w3, vv.x, c3.x); c3.y = fmaf(w3, vv.y, c3.y);
            }
        }
        __syncthreads();
    }

    float* gp = g_part + (size_t)ch*CTXN + ((size_t)bh*Uq + 4*w)*Dq + 2*lane;
    *(float2*)(gp)          = c0;
    *(float2*)(gp + Dq)     = c1;
    *(float2*)(gp + 2*Dq)   = c2;
    *(float2*)(gp + 3*Dq)   = c3;
}

// ---------------------------------------------------------------------------
// Kernel 6: reduce the 4 partials, float4-vectorized (R14 proven)
// ---------------------------------------------------------------------------
__global__ void k_reduce(float* __restrict__ ctx) {
    int i = blockIdx.x*256 + threadIdx.x;          // float4 index
    if (i < CTXN/4) {
        float4 s = ((const float4*)g_part)[i];
        #pragma unroll
        for (int c = 1; c < NCH; ++c) {
            float4 p = ((const float4*)g_part)[(size_t)c*(CTXN/4) + i];
            s.x += p.x; s.y += p.y; s.z += p.z; s.w += p.w;
        }
        ((float4*)ctx)[i] = s;
    }
}

// ---------------------------------------------------------------------------
extern "C" void kernel_launch(void* const* d_in, const int* in_sizes, int n_in,
                              void* d_out, int out_size) {
    const float* q   = (const float*)d_in[0];
    const float* k   = (const float*)d_in[1];
    const float* v   = (const float*)d_in[2];
    const int*   idx = (const int*)d_in[3];

    float* ctx  = (float*)d_out;          // (B,H,u,D) = 163840 f32
    float* attn = ctx + CTXN;             // (B,H,u,L) = 5242880 f32

    const int smemCtx = (2*64*64 + 2*Uq*64) * sizeof(float);   // 53248 B
    cudaFuncSetAttribute(k_ctx, cudaFuncAttributeMaxDynamicSharedMemorySize, smemCtx);

    k_M<<<(BH*Lq*32)/1024, 1024>>>(q, k, idx);
    k_topk<<<BH, 256>>>();
    k_scores<<<dim3(Lq/128, BH), 256>>>(q, k, attn);
    k_softmax<<<BH*Uq, 256>>>(attn);
    k_ctx<<<dim3(NCH, BH), 320, smemCtx>>>(v, attn);
    k_reduce<<<(CTXN/4 + 255)/256, 256>>>(ctx);
}

// round 16
// speedup vs baseline: 1.0659x; 1.0659x over previous
#include <cuda_runtime.h>
#include <cuda_pipeline.h>
#include <math.h>

#define Bq   8
#define Hq   8
#define Lq   2048
#define Dq   64
#define Uq   40
#define BH   64
#define CTXN (BH*Uq*Dq)
#define NCH  4

// scratch (no allocations allowed)
__device__ float g_M[BH*Lq];
__device__ int   g_top[BH*Uq];
__device__ float g_part[NCH*CTXN];

// ---------------------------------------------------------------------------
// Kernel 1: M[bh,l] = max_s(q·k[idx]) - sum_s(q·k[idx]) / L   (R8/R14 proven,
// 256-thread blocks — R15 showed 1024 regresses)
// ---------------------------------------------------------------------------
__global__ __launch_bounds__(256) void k_M(const float* __restrict__ q,
                                           const float* __restrict__ kk,
                                           const int* __restrict__ idx) {
    int gw   = (blockIdx.x * blockDim.x + threadIdx.x) >> 5;   // bh*Lq + l
    int lane = threadIdx.x & 31;
    int g = lane >> 3;          // sample slot 0..3
    int e = lane & 7;           // 32B chunk 0..7
    int bh = gw >> 11;
    int l  = gw & (Lq - 1);

    const float*  kbase = kk + (size_t)bh*Lq*Dq;
    const float4* qrow  = (const float4*)(q + ((size_t)bh*Lq + l)*Dq);

    const float4 q0 = __ldg(qrow + 2*e);
    const float4 q1 = __ldg(qrow + 2*e + 1);

    const int* irow = idx + l*Uq;
    float mx = -INFINITY, sm = 0.f;

    #pragma unroll
    for (int i = 0; i < Uq/4; ++i) {
        int j = __ldg(irow + 4*i + g);
        const float4* kr = (const float4*)(kbase + (size_t)j*Dq);
        float4 a = __ldg(kr + 2*e);
        float4 b = __ldg(kr + 2*e + 1);
        float p = q0.x*a.x;
        p = fmaf(q0.y, a.y, p); p = fmaf(q0.z, a.z, p); p = fmaf(q0.w, a.w, p);
        p = fmaf(q1.x, b.x, p); p = fmaf(q1.y, b.y, p);
        p = fmaf(q1.z, b.z, p); p = fmaf(q1.w, b.w, p);
        p += __shfl_xor_sync(0xffffffffu, p, 4);
        p += __shfl_xor_sync(0xffffffffu, p, 2);
        p += __shfl_xor_sync(0xffffffffu, p, 1);
        mx = fmaxf(mx, p); sm += p;
    }
    mx = fmaxf(mx, __shfl_xor_sync(0xffffffffu, mx, 8));
    sm += __shfl_xor_sync(0xffffffffu, sm, 8);
    mx = fmaxf(mx, __shfl_xor_sync(0xffffffffu, mx, 16));
    sm += __shfl_xor_sync(0xffffffffu, sm, 16);

    if (lane == 0) g_M[gw] = mx - sm * (1.0f / (float)Lq);
}

// ---------------------------------------------------------------------------
// Kernel 2: top-40 per (bh), per-warp top-40 + 8-way merge (R10 proven)
// ---------------------------------------------------------------------------
__global__ __launch_bounds__(256) void k_topk() {
    __shared__ float cand_v[8][Uq];
    __shared__ int   cand_i[8][Uq];
    int bh = blockIdx.x, t = threadIdx.x;
    int w = t >> 5, lane = t & 31;
    const unsigned full = 0xffffffffu;

    float vals[8]; int idxs[8];
    #pragma unroll
    for (int ii = 0; ii < 8; ++ii) {
        int i = w*256 + ii*32 + lane;
        vals[ii] = g_M[bh*Lq + i];
        idxs[ii] = i;
    }

    for (int r = 0; r < Uq; ++r) {
        float bv = vals[0]; int bi = idxs[0]; int bs = 0;
        #pragma unroll
        for (int ii = 1; ii < 8; ++ii) {
            if (vals[ii] > bv || (vals[ii] == bv && idxs[ii] < bi)) {
                bv = vals[ii]; bi = idxs[ii]; bs = ii;
            }
        }
        float wv = bv; int wi = bi;
        #pragma unroll
        for (int o = 16; o > 0; o >>= 1) {
            float xv = __shfl_xor_sync(full, wv, o);
            int   xi = __shfl_xor_sync(full, wi, o);
            if (xv > wv || (xv == wv && xi < wi)) { wv = xv; wi = xi; }
        }
        if (wi == bi) vals[bs] = -INFINITY;
        if (lane == 0) { cand_v[w][r] = wv; cand_i[w][r] = wi; }
    }
    __syncthreads();

    if (w == 0 && lane < 8) {
        int head = 0;
        float hv = cand_v[lane][0];
        int   hi = cand_i[lane][0];
        for (int r = 0; r < Uq; ++r) {
            float bv = hv; int bi = hi; int bl = lane;
            #pragma unroll
            for (int o = 4; o > 0; o >>= 1) {
                float xv = __shfl_xor_sync(0xffu, bv, o);
                int   xi = __shfl_xor_sync(0xffu, bi, o);
                int   xl = __shfl_xor_sync(0xffu, bl, o);
                if (xv > bv || (xv == bv && xi < bi)) { bv = xv; bi = xi; bl = xl; }
            }
            if (lane == 0) g_top[bh*Uq + r] = bi;
            if (lane == bl) {
                head++;
                hv = (head < Uq) ? cand_v[lane][head] : -INFINITY;
                hi = (head < Uq) ? cand_i[lane][head] : 0x7fffffff;
            }
        }
    }
}

// ---------------------------------------------------------------------------
// Kernel 3: scores, 5x4 register-tiled @ 256 threads (R6/R12 proven)
// ---------------------------------------------------------------------------
__global__ __launch_bounds__(256) void k_scores(const float* __restrict__ q,
                                                const float* __restrict__ kk,
                                                float* __restrict__ attn) {
    __shared__ float qs[Uq][68];
    __shared__ float ks[128][68];
    int bh = blockIdx.y, tile = blockIdx.x, t = threadIdx.x;
    int w = t >> 5, lane = t & 31;

    const float* qb = q  + (size_t)bh*Lq*Dq;
    const float* kb = kk + ((size_t)bh*Lq + tile*128)*Dq;

    for (int i = t; i < Uq*16; i += 256) {
        int r = i >> 4, c4 = i & 15;
        float4 val = *(const float4*)(qb + (size_t)g_top[bh*Uq + r]*Dq + c4*4);
        *(float4*)&qs[r][c4*4] = val;
    }
    for (int i = t; i < 128*16; i += 256) {
        int l = i >> 4, c4 = i & 15;
        *(float4*)&ks[l][c4*4] = ((const float4*)(kb + (size_t)l*Dq))[c4];
    }
    __syncthreads();

    float acc[5][4] = {};
    #pragma unroll 4
    for (int c = 0; c < 64; c += 4) {
        float4 kr[4];
        #pragma unroll
        for (int j = 0; j < 4; ++j) kr[j] = *(const float4*)&ks[lane + 32*j][c];
        #pragma unroll
        for (int ji = 0; ji < 5; ++ji) {
            float4 qr = *(const float4*)&qs[5*w + ji][c];
            #pragma unroll
            for (int jl = 0; jl < 4; ++jl) {
                acc[ji][jl] = fmaf(qr.x, kr[jl].x, acc[ji][jl]);
                acc[ji][jl] = fmaf(qr.y, kr[jl].y, acc[ji][jl]);
                acc[ji][jl] = fmaf(qr.z, kr[jl].z, acc[ji][jl]);
                acc[ji][jl] = fmaf(qr.w, kr[jl].w, acc[ji][jl]);
            }
        }
    }
    #pragma unroll
    for (int ji = 0; ji < 5; ++ji) {
        int i = 5*w + ji;
        #pragma unroll
        for (int jl = 0; jl < 4; ++jl)
            attn[((size_t)bh*Uq + i)*Lq + tile*128 + lane + 32*jl] = acc[ji][jl] * 0.125f;
    }
}

// ---------------------------------------------------------------------------
// Kernel 4: row softmax, shfl reductions; __expf (MUFU.EX2) on the
// latency-critical exp chain — softmax is post-selection, so only the
// 1e-3-budget outputs see the ~1e-6 fast-exp error.
// ---------------------------------------------------------------------------
__global__ __launch_bounds__(256) void k_softmax(float* __restrict__ attn) {
    __shared__ float wred[8];
    int row = blockIdx.x, t = threadIdx.x;
    int w = t >> 5, lane = t & 31;
    float* a = attn + (size_t)row * Lq;

    float4 v0 = ((float4*)a)[t];
    float4 v1 = ((float4*)a)[t + 256];

    float mx = fmaxf(fmaxf(fmaxf(v0.x, v0.y), fmaxf(v0.z, v0.w)),
                     fmaxf(fmaxf(v1.x, v1.y), fmaxf(v1.z, v1.w)));
    #pragma unroll
    for (int o = 16; o > 0; o >>= 1) mx = fmaxf(mx, __shfl_xor_sync(0xffffffffu, mx, o));
    if (lane == 0) wred[w] = mx;
    __syncthreads();
    mx = wred[0];
    #pragma unroll
    for (int j = 1; j < 8; ++j) mx = fmaxf(mx, wred[j]);
    __syncthreads();

    v0.x = __expf(v0.x - mx); v0.y = __expf(v0.y - mx);
    v0.z = __expf(v0.z - mx); v0.w = __expf(v0.w - mx);
    v1.x = __expf(v1.x - mx); v1.y = __expf(v1.y - mx);
    v1.z = __expf(v1.z - mx); v1.w = __expf(v1.w - mx);

    float s = v0.x + v0.y + v0.z + v0.w + v1.x + v1.y + v1.z + v1.w;
    #pragma unroll
    for (int o = 16; o > 0; o >>= 1) s += __shfl_xor_sync(0xffffffffu, s, o);
    if (lane == 0) wred[w] = s;
    __syncthreads();
    s = wred[0];
    #pragma unroll
    for (int j = 1; j < 8; ++j) s += wred[j];
    float inv = 1.0f / s;

    v0.x *= inv; v0.y *= inv; v0.z *= inv; v0.w *= inv;
    v1.x *= inv; v1.y *= inv; v1.z *= inv; v1.w *= inv;
    ((float4*)a)[t]       = v0;
    ((float4*)a)[t + 256] = v1;
}

// ---------------------------------------------------------------------------
// k_ctx tile fill via cp.async (R8 proven)
// ---------------------------------------------------------------------------
__device__ __forceinline__ void ctx_fill(float* vdst, float* adst,
                                         const float* __restrict__ vb,
                                         const float* __restrict__ ab,
                                         int l0, int t) {
    for (int i = t; i < 1024; i += 320) {
        int k = i >> 4, c4 = i & 15;
        __pipeline_memcpy_async(vdst + (size_t)k*64 + c4*4,
                                vb + (size_t)(l0 + k)*Dq + c4*4, 16);
    }
    for (int i = t; i < 640; i += 320) {
        int r = i >> 4, c4 = i & 15;
        __pipeline_memcpy_async(adst + (size_t)r*64 + c4*4,
                                ab + (size_t)r*Lq + l0 + c4*4, 16);
    }
    __pipeline_commit();
}

// ---------------------------------------------------------------------------
// Kernel 5: context partials, cp.async double-buffered; NCH=4 (R14 proven)
// ---------------------------------------------------------------------------
__global__ __launch_bounds__(320) void k_ctx(const float* __restrict__ v,
                                             const float* __restrict__ attn) {
    extern __shared__ float smc[];
    float* vsm0 = smc;
    float* vsm1 = smc + 4096;
    float* a_sm0 = smc + 8192;
    float* a_sm1 = smc + 8192 + 2560;
    int bh = blockIdx.y, ch = blockIdx.x, t = threadIdx.x;
    int w = t >> 5, lane = t & 31;

    const float* vb = v    + (size_t)bh*Lq*Dq;
    const float* ab = attn + (size_t)bh*Uq*Lq;

    float2 c0 = {0.f,0.f}, c1 = {0.f,0.f}, c2 = {0.f,0.f}, c3 = {0.f,0.f};

    ctx_fill(vsm0, a_sm0, vb, ab, ch*512, t);

    #pragma unroll
    for (int tl = 0; tl < 8; ++tl) {
        if (tl < 7) {
            ctx_fill((tl & 1) ? vsm0 : vsm1, (tl & 1) ? a_sm0 : a_sm1,
                     vb, ab, ch*512 + (tl+1)*64, t);
            __pipeline_wait_prior(1);
        } else {
            __pipeline_wait_prior(0);
        }
        __syncthreads();
        const float* vs = (tl & 1) ? vsm1 : vsm0;
        const float* as = (tl & 1) ? a_sm1 : a_sm0;
        #pragma unroll 4
        for (int k4 = 0; k4 < 16; ++k4) {
            float4 a0 = *(const float4*)&as[(4*w+0)*64 + 4*k4];
            float4 a1 = *(const float4*)&as[(4*w+1)*64 + 4*k4];
            float4 a2 = *(const float4*)&as[(4*w+2)*64 + 4*k4];
            float4 a3 = *(const float4*)&as[(4*w+3)*64 + 4*k4];
            #pragma unroll
            for (int j = 0; j < 4; ++j) {
                int k = 4*k4 + j;
                float2 vv = *(const float2*)&vs[(size_t)k*64 + 2*lane];
                float w0 = (j==0)?a0.x:(j==1)?a0.y:(j==2)?a0.z:a0.w;
                float w1 = (j==0)?a1.x:(j==1)?a1.y:(j==2)?a1.z:a1.w;
                float w2 = (j==0)?a2.x:(j==1)?a2.y:(j==2)?a2.z:a2.w;
                float w3 = (j==0)?a3.x:(j==1)?a3.y:(j==2)?a3.z:a3.w;
                c0.x = fmaf(w0, vv.x, c0.x); c0.y = fmaf(w0, vv.y, c0.y);
                c1.x = fmaf(w1, vv.x, c1.x); c1.y = fmaf(w1, vv.y, c1.y);
                c2.x = fmaf(w2, vv.x, c2.x); c2.y = fmaf(w2, vv.y, c2.y);
                c3.x = fmaf(w3, vv.x, c3.x); c3.y = fmaf(w3, vv.y, c3.y);
            }
        }
        __syncthreads();
    }

    float* gp = g_part + (size_t)ch*CTXN + ((size_t)bh*Uq + 4*w)*Dq + 2*lane;
    *(float2*)(gp)          = c0;
    *(float2*)(gp + Dq)     = c1;
    *(float2*)(gp + 2*Dq)   = c2;
    *(float2*)(gp + 3*Dq)   = c3;
}

// ---------------------------------------------------------------------------
// Kernel 6: reduce the 4 partials, float4-vectorized (R14 proven)
// ---------------------------------------------------------------------------
__global__ void k_reduce(float* __restrict__ ctx) {
    int i = blockIdx.x*256 + threadIdx.x;          // float4 index
    if (i < CTXN/4) {
        float4 s = ((const float4*)g_part)[i];
        #pragma unroll
        for (int c = 1; c < NCH; ++c) {
            float4 p = ((const float4*)g_part)[(size_t)c*(CTXN/4) + i];
            s.x += p.x; s.y += p.y; s.z += p.z; s.w += p.w;
        }
        ((float4*)ctx)[i] = s;
    }
}

// ---------------------------------------------------------------------------
extern "C" void kernel_launch(void* const* d_in, const int* in_sizes, int n_in,
                              void* d_out, int out_size) {
    const float* q   = (const float*)d_in[0];
    const float* k   = (const float*)d_in[1];
    const float* v   = (const float*)d_in[2];
    const int*   idx = (const int*)d_in[3];

    float* ctx  = (float*)d_out;          // (B,H,u,D) = 163840 f32
    float* attn = ctx + CTXN;             // (B,H,u,L) = 5242880 f32

    const int smemCtx = (2*64*64 + 2*Uq*64) * sizeof(float);   // 53248 B
    cudaFuncSetAttribute(k_ctx, cudaFuncAttributeMaxDynamicSharedMemorySize, smemCtx);

    k_M<<<(BH*Lq*32)/256, 256>>>(q, k, idx);
    k_topk<<<BH, 256>>>();
    k_scores<<<dim3(Lq/128, BH), 256>>>(q, k, attn);
    k_softmax<<<BH*Uq, 256>>>(attn);
    k_ctx<<<dim3(NCH, BH), 320, smemCtx>>>(v, attn);
    k_reduce<<<(CTXN/4 + 255)/256, 256>>>(ctx);
}